// round 13
// baseline (speedup 1.0000x reference)
#include <cuda_runtime.h>
#include <cfloat>

#define BB 8
#define NN 2048
#define KNBR 32
#define NPTS (BB*NN)
#define NBLK (NN/128)           // 16 tiles per dim
#define NPAIR (NBLK*(NBLK+1)/2) // 136 upper-tri block pairs

typedef unsigned long long u64;

__device__ __forceinline__ u64 pack2(float lo, float hi) {
    u64 r;
    asm("mov.b64 %0, {%1, %2};" : "=l"(r) : "f"(lo), "f"(hi));
    return r;
}
__device__ __forceinline__ float2 unpack2(u64 v) {
    float2 f;
    asm("mov.b64 {%0, %1}, %2;" : "=f"(f.x), "=f"(f.y) : "l"(v));
    return f;
}
__device__ __forceinline__ void fma2(u64& d, u64 a, u64 b) {
    asm("fma.rn.f32x2 %0, %1, %2, %0;" : "+l"(d) : "l"(a), "l"(b));
}
__device__ __forceinline__ unsigned flipkey(float f) {
    unsigned b = __float_as_uint(f);
    return (b & 0x80000000u) ? ~b : (b | 0x80000000u);
}
__device__ __forceinline__ float4 max4(float4 a, float4 b) {
    return make_float4(fmaxf(a.x, b.x), fmaxf(a.y, b.y), fmaxf(a.z, b.z), fmaxf(a.w, b.w));
}

// ---------------- scratch (static device globals; no runtime alloc) ----------
__device__ unsigned g_keys[(size_t)NPTS * NN]; // 134MB pairwise keys (monotone map of d2)
__device__ float g_sq[NPTS];
__device__ int   g_idx[NPTS * KNBR];
__device__ float g_x1[NPTS * 64];
__device__ float g_x2[NPTS * 128];
__device__ float g_xc[NPTS * 192];
__device__ float g_qp[(size_t)NPTS * 1024];  // qpT: [cg][NPTS] float4 channel groups
__device__ float g_wc[256 * 1024];           // 3 disjoint combined-weight slices

// ---------------- squared norms ----------------------------------------------
__global__ void sq_kernel(const float* __restrict__ X, float* __restrict__ sq, int C) {
    int i = blockIdx.x * blockDim.x + threadIdx.x;
    if (i < NPTS) {
        const float* r = X + (size_t)i * C;
        float s = 0.f;
        for (int c = 0; c < C; c++) s += r[c] * r[c];
        sq[i] = s;
    }
}

// ---------------- pairwise d2 keys, symmetric, FFMA2 inner loop ---------------
__global__ void __launch_bounds__(256, 2)
d2sym_kernel(const float* __restrict__ X, const float* __restrict__ sq,
             unsigned* __restrict__ keys, int C) {
    __shared__ __align__(16) float As[16][132];
    __shared__ __align__(16) float Bs[16][132];
    int b = blockIdx.y;
    int rem = blockIdx.x, bi = 0;
    while (rem >= NBLK - bi) { rem -= NBLK - bi; bi++; }
    int bj = bi + rem;
    int row0 = bi * 128, col0 = bj * 128;

    const float* Xb = X + (size_t)b * NN * C;
    int tid = threadIdx.x;
    int ty = tid >> 4, tx = tid & 15;
    u64 acc2[8][4];
#pragma unroll
    for (int i = 0; i < 8; i++)
#pragma unroll
        for (int j = 0; j < 4; j++) acc2[i][j] = 0ull;

    int kk = tid & 15, i0 = tid >> 4;

    if (C <= 16) {
        bool kin = (kk < C);
#pragma unroll
        for (int u = 0; u < 8; u++) {
            int i = i0 + (u << 4);
            As[kk][i] = kin ? Xb[(size_t)(row0 + i) * C + kk] : 0.f;
            Bs[kk][i] = kin ? Xb[(size_t)(col0 + i) * C + kk] : 0.f;
        }
        __syncthreads();
        for (int t = 0; t < C; t++) {
            float a[8], bv[8];
            *(float4*)&a[0]  = *(const float4*)&As[t][ty << 2];
            *(float4*)&a[4]  = *(const float4*)&As[t][64 + (ty << 2)];
            *(float4*)&bv[0] = *(const float4*)&Bs[t][tx << 2];
            *(float4*)&bv[4] = *(const float4*)&Bs[t][64 + (tx << 2)];
            u64 b2[4];
#pragma unroll
            for (int j = 0; j < 4; j++) b2[j] = pack2(bv[2 * j], bv[2 * j + 1]);
#pragma unroll
            for (int i = 0; i < 8; i++) {
                u64 a2 = pack2(a[i], a[i]);
#pragma unroll
                for (int j = 0; j < 4; j++) fma2(acc2[i][j], a2, b2[j]);
            }
        }
        __syncthreads();
    } else {
        for (int k0 = 0; k0 < C; k0 += 16) {
            int k = k0 + kk;
#pragma unroll
            for (int u = 0; u < 8; u++) {
                int i = i0 + (u << 4);
                As[kk][i] = Xb[(size_t)(row0 + i) * C + k];
                Bs[kk][i] = Xb[(size_t)(col0 + i) * C + k];
            }
            __syncthreads();
#pragma unroll
            for (int t = 0; t < 16; t++) {
                float a[8], bv[8];
                *(float4*)&a[0]  = *(const float4*)&As[t][ty << 2];
                *(float4*)&a[4]  = *(const float4*)&As[t][64 + (ty << 2)];
                *(float4*)&bv[0] = *(const float4*)&Bs[t][tx << 2];
                *(float4*)&bv[4] = *(const float4*)&Bs[t][64 + (tx << 2)];
                u64 b2[4];
#pragma unroll
                for (int j = 0; j < 4; j++) b2[j] = pack2(bv[2 * j], bv[2 * j + 1]);
#pragma unroll
                for (int i = 0; i < 8; i++) {
                    u64 a2 = pack2(a[i], a[i]);
#pragma unroll
                    for (int j = 0; j < 4; j++) fma2(acc2[i][j], a2, b2[j]);
                }
            }
            __syncthreads();
        }
    }

    unsigned kv[8][8];
#pragma unroll
    for (int i = 0; i < 8; i++) {
        int r = row0 + ((i < 4) ? ((ty << 2) + i) : (64 + (ty << 2) + i - 4));
        float sqr = sq[b * NN + r];
#pragma unroll
        for (int j = 0; j < 4; j++) {
            float2 f = unpack2(acc2[i][j]);
            int c0 = col0 + ((2*j < 4) ? ((tx << 2) + 2*j) : (64 + (tx << 2) + 2*j - 4));
            int c1 = col0 + ((2*j+1 < 4) ? ((tx << 2) + 2*j+1) : (64 + (tx << 2) + 2*j+1 - 4));
            float v0 = sqr + sq[b * NN + c0] - 2.f * f.x;
            float v1 = sqr + sq[b * NN + c1] - 2.f * f.y;
            if (r == c0) v0 = FLT_MAX;
            if (r == c1) v1 = FLT_MAX;
            kv[i][2*j]   = flipkey(v0);
            kv[i][2*j+1] = flipkey(v1);
        }
    }

    unsigned* kb = keys + (size_t)b * NN * NN;
#pragma unroll
    for (int i = 0; i < 8; i++) {
        int r = row0 + ((i < 4) ? ((ty << 2) + i) : (64 + (ty << 2) + i - 4));
        uint4 v0 = make_uint4(kv[i][0], kv[i][1], kv[i][2], kv[i][3]);
        uint4 v1 = make_uint4(kv[i][4], kv[i][5], kv[i][6], kv[i][7]);
        __stcs((uint4*)&kb[(size_t)r * NN + col0 + (tx << 2)],      v0);
        __stcs((uint4*)&kb[(size_t)r * NN + col0 + 64 + (tx << 2)], v1);
    }
    if (bi != bj) {
#pragma unroll
        for (int j = 0; j < 8; j++) {
            int c = col0 + ((j < 4) ? ((tx << 2) + j) : (64 + (tx << 2) + j - 4));
            uint4 lo = make_uint4(kv[0][j], kv[1][j], kv[2][j], kv[3][j]);
            uint4 hi = make_uint4(kv[4][j], kv[5][j], kv[6][j], kv[7][j]);
            __stcs((uint4*)&kb[(size_t)c * NN + row0 + (ty << 2)],      lo);
            __stcs((uint4*)&kb[(size_t)c * NN + row0 + 64 + (ty << 2)], hi);
        }
    }
}

// ---------------- top-K via 4-pass (8-bit) radix select ------------------------
__global__ void __launch_bounds__(256)
knn_kernel(const unsigned* __restrict__ keys_g, int* __restrict__ idxout) {
    __shared__ int hist[2048];      // 256 used as bins; full 2048 reused as tie buffer
    __shared__ int wsum[8], wsumex[8];
    __shared__ int ctrlB, ctrlBelow;
    __shared__ int cnt, eqcnt;

    int p = blockIdx.x;
    int t = threadIdx.x, lane = t & 31, wid = t >> 5;

    const uint4* row4 = (const uint4*)(keys_g + (size_t)p * NN);
    unsigned key[8];
#pragma unroll
    for (int u = 0; u < 2; u++) {
        uint4 f = __ldcs(&row4[t + (u << 8)]);
        key[u * 4 + 0] = f.x; key[u * 4 + 1] = f.y;
        key[u * 4 + 2] = f.z; key[u * 4 + 3] = f.w;
    }

    unsigned pval = 0, pmask = 0;
    int base = 0;
#pragma unroll
    for (int pass = 0; pass < 4; pass++) {
        const int shift = 24 - (pass << 3);
        hist[t] = 0;
        __syncthreads();
        if (pass == 0) {
#pragma unroll
            for (int e = 0; e < 8; e++) {
                int bin = key[e] >> 24;
                unsigned peers = __match_any_sync(0xffffffffu, bin);
                int leader = __ffs(peers) - 1;
                if (lane == leader) atomicAdd(&hist[bin], __popc(peers));
            }
        } else {
#pragma unroll
            for (int e = 0; e < 8; e++) {
                unsigned k = key[e];
                if ((k & pmask) == pval) atomicAdd(&hist[(k >> shift) & 255], 1);
            }
        }
        __syncthreads();
        int s = hist[t];
        int incl = s;
#pragma unroll
        for (int off = 1; off < 32; off <<= 1) {
            int n = __shfl_up_sync(0xffffffffu, incl, off);
            if (lane >= off) incl += n;
        }
        if (lane == 31) wsum[wid] = incl;
        __syncthreads();
        if (t == 0) {
            int run = 0;
            for (int w = 0; w < 8; w++) { wsumex[w] = run; run += wsum[w]; }
        }
        __syncthreads();
        int excl = wsumex[wid] + incl - s;
        int need = KNBR - base;
        if (excl < need && need <= excl + s) {
            ctrlB = t; ctrlBelow = excl;
        }
        __syncthreads();
        base += ctrlBelow;
        pval |= ((unsigned)ctrlB) << shift;
        pmask |= 255u << shift;
        __syncthreads();
    }

    const unsigned T = pval;
    if (t == 0) { cnt = 0; eqcnt = 0; }
    __syncthreads();
#pragma unroll
    for (int e = 0; e < 8; e++) {
        unsigned k = key[e];
        int i = (t << 2) + ((e >> 2) << 10) + (e & 3);
        if (k < T) {
            int pos = atomicAdd(&cnt, 1);
            idxout[p * KNBR + pos] = i;
        } else if (k == T) {
            int q = atomicAdd(&eqcnt, 1);
            hist[q] = i;
        }
    }
    __syncthreads();
    int c = cnt, E = eqcnt, tn = KNBR - c;
    if (E == tn) {
        for (int j = t; j < E; j += 256) idxout[p * KNBR + c + j] = hist[j];
    } else {
        for (int j = t; j < E; j += 256) {
            int mi = hist[j], r = 0;
            for (int q = 0; q < E; q++) r += (hist[q] < mi);
            if (r < tn) idxout[p * KNBR + c + r] = mi;
        }
    }
}

// ---------------- combined weight prep: wc = [Wb | Wa - Wb] -------------------
__global__ void prepw_kernel(const float* __restrict__ W, float* __restrict__ wc,
                             int C, int Cout) {
    int i = blockIdx.x * blockDim.x + threadIdx.x;
    if (i < C * Cout) {
        int c = i / Cout, d = i % Cout;
        float wa = W[c * Cout + d];
        float wb = W[(C + c) * Cout + d];
        wc[c * (2 * Cout) + d] = wb;
        wc[c * (2 * Cout) + Cout + d] = wa - wb;
    }
}

// ---------------- GEMM with FFMA2, output written TRANSPOSED -------------------
// qpT4[cg * NPTS + row] = float4 of columns (4*cg .. 4*cg+3) for this row.
__global__ void __launch_bounds__(256, 2)
gemm_kernel(const float* __restrict__ A, const float* __restrict__ Bm,
            float4* __restrict__ qpT4, int Kd, int Nd) {
    __shared__ __align__(16) float As[16][132];
    __shared__ __align__(16) float Bs[16][132];
    int row0 = blockIdx.y * 128, col0 = blockIdx.x * 128;
    int tid = threadIdx.x;
    int ty = tid >> 4, tx = tid & 15;
    u64 acc2[8][4];
#pragma unroll
    for (int i = 0; i < 8; i++)
#pragma unroll
        for (int j = 0; j < 4; j++) acc2[i][j] = 0ull;

    int kk = tid & 15, i0 = tid >> 4;
    int j0 = tid & 127, kb = tid >> 7;

    for (int k0 = 0; k0 < Kd; k0 += 16) {
        int k = k0 + kk;
        bool kin = (k < Kd);
#pragma unroll
        for (int u = 0; u < 8; u++) {
            int i = i0 + (u << 4);
            As[kk][i] = kin ? A[(size_t)(row0 + i) * Kd + k] : 0.f;
        }
#pragma unroll
        for (int u = 0; u < 8; u++) {
            int kr = kb + (u << 1);
            int kg = k0 + kr;
            Bs[kr][j0] = (kg < Kd) ? Bm[(size_t)kg * Nd + col0 + j0] : 0.f;
        }
        __syncthreads();
#pragma unroll
        for (int t = 0; t < 16; t++) {
            float a[8], bv[8];
            *(float4*)&a[0]  = *(const float4*)&As[t][ty << 2];
            *(float4*)&a[4]  = *(const float4*)&As[t][64 + (ty << 2)];
            *(float4*)&bv[0] = *(const float4*)&Bs[t][tx << 2];
            *(float4*)&bv[4] = *(const float4*)&Bs[t][64 + (tx << 2)];
            u64 b2[4];
#pragma unroll
            for (int j = 0; j < 4; j++) b2[j] = pack2(bv[2 * j], bv[2 * j + 1]);
#pragma unroll
            for (int i = 0; i < 8; i++) {
                u64 a2 = pack2(a[i], a[i]);
#pragma unroll
                for (int j = 0; j < 4; j++) fma2(acc2[i][j], a2, b2[j]);
            }
        }
        __syncthreads();
    }
    int cg0 = (col0 >> 2) + tx;
#pragma unroll
    for (int i = 0; i < 8; i++) {
        int r = row0 + ((i < 4) ? ((ty << 2) + i) : (64 + (ty << 2) + i - 4));
        float2 f0 = unpack2(acc2[i][0]), f1 = unpack2(acc2[i][1]);
        float2 f2 = unpack2(acc2[i][2]), f3 = unpack2(acc2[i][3]);
        float4 v0 = make_float4(f0.x, f0.y, f1.x, f1.y);
        float4 v1 = make_float4(f2.x, f2.y, f3.x, f3.y);
        qpT4[(size_t)cg0 * NPTS + r]        = v0;
        qpT4[(size_t)(cg0 + 16) * NPTS + r] = v1;
    }
}

// ---------------- gather-max, smem-staged from transposed q --------------------
// grid (c4, BB), 256 threads. Block stages its contiguous 2048-point q-slice
// (32KB) then all neighbor maxes run from smem.
__global__ void __launch_bounds__(256)
gather_kernel(const float4* __restrict__ qpT4, const int* __restrict__ idx,
              const float4* __restrict__ bias4, float* __restrict__ out,
              int c4, int relu) {
    __shared__ __align__(16) float4 qs[NN];
    int d = blockIdx.x, b = blockIdx.y;
    size_t base = (size_t)b * NN;

    for (int i = threadIdx.x; i < NN; i += 256)
        qs[i] = qpT4[(size_t)d * NPTS + base + i];
    __syncthreads();

    float4 bb = bias4[d];
#pragma unroll
    for (int u = 0; u < NN / 256; u++) {
        int p = (int)base + threadIdx.x + (u << 8);
        const int4* ip = (const int4*)(idx + (size_t)p * KNBR);
        float4 m = make_float4(-FLT_MAX, -FLT_MAX, -FLT_MAX, -FLT_MAX);
#pragma unroll
        for (int w = 0; w < 8; w++) {
            int4 nb = ip[w];
            m = max4(m, qs[nb.x]);
            m = max4(m, qs[nb.y]);
            m = max4(m, qs[nb.z]);
            m = max4(m, qs[nb.w]);
        }
        float4 pp = qpT4[(size_t)(c4 + d) * NPTS + p];
        float4 r;
        r.x = pp.x + bb.x + m.x; r.y = pp.y + bb.y + m.y;
        r.z = pp.z + bb.z + m.z; r.w = pp.w + bb.w + m.w;
        if (relu) {
            r.x = fmaxf(r.x, 0.f); r.y = fmaxf(r.y, 0.f);
            r.z = fmaxf(r.z, 0.f); r.w = fmaxf(r.w, 0.f);
        }
        ((float4*)out)[(size_t)p * c4 + d] = r;
    }
}

// ---------------- concat x1 | x2 (float4) --------------------------------------
__global__ void concat_kernel(const float* __restrict__ x1, const float* __restrict__ x2,
                              float* __restrict__ xc) {
    int i = blockIdx.x * blockDim.x + threadIdx.x;
    if (i < NPTS * 48) {
        int p = i / 48, c = i % 48;
        float4 v = (c < 16) ? ((const float4*)x1)[p * 16 + c]
                            : ((const float4*)x2)[p * 32 + (c - 16)];
        ((float4*)xc)[i] = v;
    }
}

// ---------------- launch (round-9 two-stream schedule) -------------------------
extern "C" void kernel_launch(void* const* d_in, const int* in_sizes, int n_in,
                              void* d_out, int out_size) {
    const float* x  = (const float*)d_in[0];
    const float* W1 = (const float*)d_in[1];
    const float* b1 = (const float*)d_in[2];
    const float* W2 = (const float*)d_in[3];
    const float* b2 = (const float*)d_in[4];
    const float* W3 = (const float*)d_in[5];
    const float* b3 = (const float*)d_in[6];
    float* out = (float*)d_out;

    float *sqp, *x1, *x2, *xc, *qp, *wc;
    unsigned* keys;
    int* idxp;
    cudaGetSymbolAddress((void**)&keys, g_keys);
    cudaGetSymbolAddress((void**)&sqp,  g_sq);
    cudaGetSymbolAddress((void**)&idxp, g_idx);
    cudaGetSymbolAddress((void**)&x1,   g_x1);
    cudaGetSymbolAddress((void**)&x2,   g_x2);
    cudaGetSymbolAddress((void**)&xc,   g_xc);
    cudaGetSymbolAddress((void**)&qp,   g_qp);
    cudaGetSymbolAddress((void**)&wc,   g_wc);
    float4* qpT4 = (float4*)qp;

    float* wc3 = wc;            // 192*1024
    float* wc2 = wc + 196608;   // 64*256
    float* wc1 = wc + 212992;   // 3*128

    static cudaStream_t s1 = nullptr;
    static cudaEvent_t ev[8];
    if (!s1) {
        cudaStreamCreateWithFlags(&s1, cudaStreamNonBlocking);
        for (int i = 0; i < 8; i++) cudaEventCreateWithFlags(&ev[i], cudaEventDisableTiming);
    }

    dim3 symgrid(NPAIR, BB);

    // fork: side stream handles weight prep + feature GEMM chain
    cudaEventRecord(ev[0], 0);
    cudaStreamWaitEvent(s1, ev[0], 0);

    prepw_kernel<<<(3 * 64 + 255) / 256, 256, 0, s1>>>(W1, wc1, 3, 64);
    prepw_kernel<<<(64 * 128 + 255) / 256, 256, 0, s1>>>(W2, wc2, 64, 128);
    prepw_kernel<<<(192 * 512 + 255) / 256, 256, 0, s1>>>(W3, wc3, 192, 512);
    gemm_kernel<<<dim3(1, NPTS / 128), 256, 0, s1>>>(x, wc1, qpT4, 3, 128);
    cudaEventRecord(ev[1], s1);

    // ---- stage 1 selection chain (default stream)
    sq_kernel<<<(NPTS + 255) / 256, 256>>>(x, sqp, 3);
    d2sym_kernel<<<symgrid, 256>>>(x, sqp, keys, 3);
    knn_kernel<<<NPTS, 256>>>(keys, idxp);
    cudaStreamWaitEvent(0, ev[1], 0);
    gather_kernel<<<dim3(16, BB), 256>>>(qpT4, idxp, (const float4*)b1, x1, 16, 1);
    cudaEventRecord(ev[2], 0);                 // x1 ready, qp free

    // side: gemm2 (reads x1, writes qpT)
    cudaStreamWaitEvent(s1, ev[2], 0);
    gemm_kernel<<<dim3(2, NPTS / 128), 256, 0, s1>>>(x1, wc2, qpT4, 64, 256);
    cudaEventRecord(ev[3], s1);

    // ---- stage 2 selection chain
    sq_kernel<<<(NPTS + 255) / 256, 256>>>(x1, sqp, 64);
    d2sym_kernel<<<symgrid, 256>>>(x1, sqp, keys, 64);
    knn_kernel<<<NPTS, 256>>>(keys, idxp);
    cudaStreamWaitEvent(0, ev[3], 0);
    gather_kernel<<<dim3(32, BB), 256>>>(qpT4, idxp, (const float4*)b2, x2, 32, 1);
    cudaEventRecord(ev[4], 0);                 // x2 ready, qp free

    // side: concat + gemm3
    cudaStreamWaitEvent(s1, ev[4], 0);
    concat_kernel<<<(NPTS * 48 + 255) / 256, 256, 0, s1>>>(x1, x2, xc);
    gemm_kernel<<<dim3(8, NPTS / 128), 256, 0, s1>>>(xc, wc3, qpT4, 192, 1024);
    cudaEventRecord(ev[5], s1);

    // ---- stage 3 selection chain
    sq_kernel<<<(NPTS + 255) / 256, 256>>>(x2, sqp, 128);
    d2sym_kernel<<<symgrid, 256>>>(x2, sqp, keys, 128);
    knn_kernel<<<NPTS, 256>>>(keys, idxp);
    cudaStreamWaitEvent(0, ev[5], 0);
    gather_kernel<<<dim3(128, BB), 256>>>(qpT4, idxp, (const float4*)b3, out, 128, 0);
}

// round 14
// speedup vs baseline: 1.0398x; 1.0398x over previous
#include <cuda_runtime.h>
#include <cfloat>

#define BB 8
#define NN 2048
#define KNBR 32
#define NPTS (BB*NN)
#define NBLK (NN/128)           // 16 tiles per dim
#define NPAIR (NBLK*(NBLK+1)/2) // 136 upper-tri block pairs

typedef unsigned long long u64;

__device__ __forceinline__ u64 pack2(float lo, float hi) {
    u64 r;
    asm("mov.b64 %0, {%1, %2};" : "=l"(r) : "f"(lo), "f"(hi));
    return r;
}
__device__ __forceinline__ float2 unpack2(u64 v) {
    float2 f;
    asm("mov.b64 {%0, %1}, %2;" : "=f"(f.x), "=f"(f.y) : "l"(v));
    return f;
}
__device__ __forceinline__ void fma2(u64& d, u64 a, u64 b) {
    asm("fma.rn.f32x2 %0, %1, %2, %0;" : "+l"(d) : "l"(a), "l"(b));
}
__device__ __forceinline__ unsigned flipkey(float f) {
    unsigned b = __float_as_uint(f);
    return (b & 0x80000000u) ? ~b : (b | 0x80000000u);
}
__device__ __forceinline__ float4 max4(float4 a, float4 b) {
    return make_float4(fmaxf(a.x, b.x), fmaxf(a.y, b.y), fmaxf(a.z, b.z), fmaxf(a.w, b.w));
}

// ---------------- scratch (static device globals; no runtime alloc) ----------
__device__ unsigned g_keys[(size_t)NPTS * NN]; // 134MB keys; reused as outT scratch in stage 3
__device__ float g_sq[NPTS];
__device__ int   g_idx[NPTS * KNBR];
__device__ float g_xc[NPTS * 192];           // xcT: float4[48][NPTS]; x1T=cg 0..15, x2T=cg 16..47
__device__ float g_qp[(size_t)NPTS * 1024];  // qpT: float4[2*c4][NPTS]
__device__ float g_wc[256 * 1024];           // 3 disjoint combined-weight slices

// ---------------- squared norms (scalar layout, stage 1) ----------------------
__global__ void sq_kernel(const float* __restrict__ X, float* __restrict__ sq, int C) {
    int i = blockIdx.x * blockDim.x + threadIdx.x;
    if (i < NPTS) {
        const float* r = X + (size_t)i * C;
        float s = 0.f;
        for (int c = 0; c < C; c++) s += r[c] * r[c];
        sq[i] = s;
    }
}

// ---------------- squared norms (T layout) -------------------------------------
__global__ void sqT_kernel(const float4* __restrict__ XT4, float* __restrict__ sq, int ncg) {
    int i = blockIdx.x * blockDim.x + threadIdx.x;
    if (i < NPTS) {
        float s = 0.f;
        for (int cg = 0; cg < ncg; cg++) {
            float4 v = XT4[(size_t)cg * NPTS + i];
            s += v.x * v.x + v.y * v.y + v.z * v.z + v.w * v.w;
        }
        sq[i] = s;
    }
}

// ---------------- pairwise d2 keys, symmetric, FFMA2 ---------------------------
// C<=16: scalar X layout [point][C]. Otherwise: XT4 layout float4[cg][NPTS].
__global__ void __launch_bounds__(256, 2)
d2sym_kernel(const float* __restrict__ X, const float4* __restrict__ XT4,
             const float* __restrict__ sq, unsigned* __restrict__ keys, int C) {
    __shared__ __align__(16) float As[16][132];
    __shared__ __align__(16) float Bs[16][132];
    int b = blockIdx.y;
    int rem = blockIdx.x, bi = 0;
    while (rem >= NBLK - bi) { rem -= NBLK - bi; bi++; }
    int bj = bi + rem;
    int row0 = bi * 128, col0 = bj * 128;
    int pbase = b * NN;

    int tid = threadIdx.x;
    int ty = tid >> 4, tx = tid & 15;
    u64 acc2[8][4];
#pragma unroll
    for (int i = 0; i < 8; i++)
#pragma unroll
        for (int j = 0; j < 4; j++) acc2[i][j] = 0ull;

    if (C <= 16) {
        const float* Xb = X + (size_t)pbase * C;
        int kk = tid & 15, i0 = tid >> 4;
        bool kin = (kk < C);
#pragma unroll
        for (int u = 0; u < 8; u++) {
            int i = i0 + (u << 4);
            As[kk][i] = kin ? Xb[(size_t)(row0 + i) * C + kk] : 0.f;
            Bs[kk][i] = kin ? Xb[(size_t)(col0 + i) * C + kk] : 0.f;
        }
        __syncthreads();
        for (int t = 0; t < C; t++) {
            float a[8], bv[8];
            *(float4*)&a[0]  = *(const float4*)&As[t][ty << 2];
            *(float4*)&a[4]  = *(const float4*)&As[t][64 + (ty << 2)];
            *(float4*)&bv[0] = *(const float4*)&Bs[t][tx << 2];
            *(float4*)&bv[4] = *(const float4*)&Bs[t][64 + (tx << 2)];
            u64 b2[4];
#pragma unroll
            for (int j = 0; j < 4; j++) b2[j] = pack2(bv[2 * j], bv[2 * j + 1]);
#pragma unroll
            for (int i = 0; i < 8; i++) {
                u64 a2 = pack2(a[i], a[i]);
#pragma unroll
                for (int j = 0; j < 4; j++) fma2(acc2[i][j], a2, b2[j]);
            }
        }
        __syncthreads();
    } else {
        int cg = tid & 3, ii = tid >> 2;     // ii 0..63
        for (int k0 = 0; k0 < C; k0 += 16) {
            int cgg = (k0 >> 2) + cg;
#pragma unroll
            for (int u = 0; u < 2; u++) {
                int i = ii + (u << 6);
                float4 va = XT4[(size_t)cgg * NPTS + pbase + row0 + i];
                As[cg * 4 + 0][i] = va.x; As[cg * 4 + 1][i] = va.y;
                As[cg * 4 + 2][i] = va.z; As[cg * 4 + 3][i] = va.w;
                float4 vb = XT4[(size_t)cgg * NPTS + pbase + col0 + i];
                Bs[cg * 4 + 0][i] = vb.x; Bs[cg * 4 + 1][i] = vb.y;
                Bs[cg * 4 + 2][i] = vb.z; Bs[cg * 4 + 3][i] = vb.w;
            }
            __syncthreads();
#pragma unroll
            for (int t = 0; t < 16; t++) {
                float a[8], bv[8];
                *(float4*)&a[0]  = *(const float4*)&As[t][ty << 2];
                *(float4*)&a[4]  = *(const float4*)&As[t][64 + (ty << 2)];
                *(float4*)&bv[0] = *(const float4*)&Bs[t][tx << 2];
                *(float4*)&bv[4] = *(const float4*)&Bs[t][64 + (tx << 2)];
                u64 b2[4];
#pragma unroll
                for (int j = 0; j < 4; j++) b2[j] = pack2(bv[2 * j], bv[2 * j + 1]);
#pragma unroll
                for (int i = 0; i < 8; i++) {
                    u64 a2 = pack2(a[i], a[i]);
#pragma unroll
                    for (int j = 0; j < 4; j++) fma2(acc2[i][j], a2, b2[j]);
                }
            }
            __syncthreads();
        }
    }

    unsigned kv[8][8];
#pragma unroll
    for (int i = 0; i < 8; i++) {
        int r = row0 + ((i < 4) ? ((ty << 2) + i) : (64 + (ty << 2) + i - 4));
        float sqr = sq[pbase + r];
#pragma unroll
        for (int j = 0; j < 4; j++) {
            float2 f = unpack2(acc2[i][j]);
            int c0 = col0 + ((2*j < 4) ? ((tx << 2) + 2*j) : (64 + (tx << 2) + 2*j - 4));
            int c1 = col0 + ((2*j+1 < 4) ? ((tx << 2) + 2*j+1) : (64 + (tx << 2) + 2*j+1 - 4));
            float v0 = sqr + sq[pbase + c0] - 2.f * f.x;
            float v1 = sqr + sq[pbase + c1] - 2.f * f.y;
            if (r == c0) v0 = FLT_MAX;
            if (r == c1) v1 = FLT_MAX;
            kv[i][2*j]   = flipkey(v0);
            kv[i][2*j+1] = flipkey(v1);
        }
    }

    unsigned* kb = keys + (size_t)b * NN * NN;
#pragma unroll
    for (int i = 0; i < 8; i++) {
        int r = row0 + ((i < 4) ? ((ty << 2) + i) : (64 + (ty << 2) + i - 4));
        uint4 v0 = make_uint4(kv[i][0], kv[i][1], kv[i][2], kv[i][3]);
        uint4 v1 = make_uint4(kv[i][4], kv[i][5], kv[i][6], kv[i][7]);
        __stcs((uint4*)&kb[(size_t)r * NN + col0 + (tx << 2)],      v0);
        __stcs((uint4*)&kb[(size_t)r * NN + col0 + 64 + (tx << 2)], v1);
    }
    if (bi != bj) {
#pragma unroll
        for (int j = 0; j < 8; j++) {
            int c = col0 + ((j < 4) ? ((tx << 2) + j) : (64 + (tx << 2) + j - 4));
            uint4 lo = make_uint4(kv[0][j], kv[1][j], kv[2][j], kv[3][j]);
            uint4 hi = make_uint4(kv[4][j], kv[5][j], kv[6][j], kv[7][j]);
            __stcs((uint4*)&kb[(size_t)c * NN + row0 + (ty << 2)],      lo);
            __stcs((uint4*)&kb[(size_t)c * NN + row0 + 64 + (ty << 2)], hi);
        }
    }
}

// ---------------- top-K via 4-pass (8-bit) radix select ------------------------
__global__ void __launch_bounds__(256)
knn_kernel(const unsigned* __restrict__ keys_g, int* __restrict__ idxout) {
    __shared__ int hist[2048];
    __shared__ int wsum[8], wsumex[8];
    __shared__ int ctrlB, ctrlBelow;
    __shared__ int cnt, eqcnt;

    int p = blockIdx.x;
    int t = threadIdx.x, lane = t & 31, wid = t >> 5;

    const uint4* row4 = (const uint4*)(keys_g + (size_t)p * NN);
    unsigned key[8];
#pragma unroll
    for (int u = 0; u < 2; u++) {
        uint4 f = __ldcs(&row4[t + (u << 8)]);
        key[u * 4 + 0] = f.x; key[u * 4 + 1] = f.y;
        key[u * 4 + 2] = f.z; key[u * 4 + 3] = f.w;
    }

    unsigned pval = 0, pmask = 0;
    int base = 0;
#pragma unroll
    for (int pass = 0; pass < 4; pass++) {
        const int shift = 24 - (pass << 3);
        hist[t] = 0;
        __syncthreads();
        if (pass == 0) {
#pragma unroll
            for (int e = 0; e < 8; e++) {
                int bin = key[e] >> 24;
                unsigned peers = __match_any_sync(0xffffffffu, bin);
                int leader = __ffs(peers) - 1;
                if (lane == leader) atomicAdd(&hist[bin], __popc(peers));
            }
        } else {
#pragma unroll
            for (int e = 0; e < 8; e++) {
                unsigned k = key[e];
                if ((k & pmask) == pval) atomicAdd(&hist[(k >> shift) & 255], 1);
            }
        }
        __syncthreads();
        int s = hist[t];
        int incl = s;
#pragma unroll
        for (int off = 1; off < 32; off <<= 1) {
            int n = __shfl_up_sync(0xffffffffu, incl, off);
            if (lane >= off) incl += n;
        }
        if (lane == 31) wsum[wid] = incl;
        __syncthreads();
        if (t == 0) {
            int run = 0;
            for (int w = 0; w < 8; w++) { wsumex[w] = run; run += wsum[w]; }
        }
        __syncthreads();
        int excl = wsumex[wid] + incl - s;
        int need = KNBR - base;
        if (excl < need && need <= excl + s) {
            ctrlB = t; ctrlBelow = excl;
        }
        __syncthreads();
        base += ctrlBelow;
        pval |= ((unsigned)ctrlB) << shift;
        pmask |= 255u << shift;
        __syncthreads();
    }

    const unsigned T = pval;
    if (t == 0) { cnt = 0; eqcnt = 0; }
    __syncthreads();
#pragma unroll
    for (int e = 0; e < 8; e++) {
        unsigned k = key[e];
        int i = (t << 2) + ((e >> 2) << 10) + (e & 3);
        if (k < T) {
            int pos = atomicAdd(&cnt, 1);
            idxout[p * KNBR + pos] = i;
        } else if (k == T) {
            int q = atomicAdd(&eqcnt, 1);
            hist[q] = i;
        }
    }
    __syncthreads();
    int c = cnt, E = eqcnt, tn = KNBR - c;
    if (E == tn) {
        for (int j = t; j < E; j += 256) idxout[p * KNBR + c + j] = hist[j];
    } else {
        for (int j = t; j < E; j += 256) {
            int mi = hist[j], r = 0;
            for (int q = 0; q < E; q++) r += (hist[q] < mi);
            if (r < tn) idxout[p * KNBR + c + r] = mi;
        }
    }
}

// ---------------- combined weight prep: wc = [Wb | Wa - Wb] -------------------
__global__ void prepw_kernel(const float* __restrict__ W, float* __restrict__ wc,
                             int C, int Cout) {
    int i = blockIdx.x * blockDim.x + threadIdx.x;
    if (i < C * Cout) {
        int c = i / Cout, d = i % Cout;
        float wa = W[c * Cout + d];
        float wb = W[(C + c) * Cout + d];
        wc[c * (2 * Cout) + d] = wb;
        wc[c * (2 * Cout) + Cout + d] = wa - wb;
    }
}

// ---------------- GEMM (FFMA2), T-layout output via smem-staged epilogue -------
// A: scalar [point][Kd] if atmode==0, else AT4 float4[cg][NPTS].
// Output qpT4[cg][NPTS], stores coalesced along points.
__global__ void __launch_bounds__(256, 2)
gemm_kernel(const float* __restrict__ A, const float4* __restrict__ AT4,
            const float* __restrict__ Bm, float4* __restrict__ qpT4,
            int Kd, int Nd, int atmode) {
    __shared__ __align__(16) float As[16][132];
    __shared__ __align__(16) float Bs[16][132];
    __shared__ __align__(16) float buf[128][17];
    int row0 = blockIdx.y * 128, col0 = blockIdx.x * 128;
    int tid = threadIdx.x;
    int ty = tid >> 4, tx = tid & 15;
    u64 acc2[8][4];
#pragma unroll
    for (int i = 0; i < 8; i++)
#pragma unroll
        for (int j = 0; j < 4; j++) acc2[i][j] = 0ull;

    int j0 = tid & 127, kb = tid >> 7;

    for (int k0 = 0; k0 < Kd; k0 += 16) {
        if (atmode) {
            int cg = tid & 3, ii = tid >> 2;
            int cgg = (k0 >> 2) + cg;
#pragma unroll
            for (int u = 0; u < 2; u++) {
                int i = ii + (u << 6);
                float4 va = AT4[(size_t)cgg * NPTS + row0 + i];
                As[cg * 4 + 0][i] = va.x; As[cg * 4 + 1][i] = va.y;
                As[cg * 4 + 2][i] = va.z; As[cg * 4 + 3][i] = va.w;
            }
        } else {
            int kk = tid & 15, i0 = tid >> 4;
            int k = k0 + kk;
            bool kin = (k < Kd);
#pragma unroll
            for (int u = 0; u < 8; u++) {
                int i = i0 + (u << 4);
                As[kk][i] = kin ? A[(size_t)(row0 + i) * Kd + k] : 0.f;
            }
        }
#pragma unroll
        for (int u = 0; u < 8; u++) {
            int kr = kb + (u << 1);
            int kg = k0 + kr;
            Bs[kr][j0] = (kg < Kd) ? Bm[(size_t)kg * Nd + col0 + j0] : 0.f;
        }
        __syncthreads();
#pragma unroll
        for (int t = 0; t < 16; t++) {
            float a[8], bv[8];
            *(float4*)&a[0]  = *(const float4*)&As[t][ty << 2];
            *(float4*)&a[4]  = *(const float4*)&As[t][64 + (ty << 2)];
            *(float4*)&bv[0] = *(const float4*)&Bs[t][tx << 2];
            *(float4*)&bv[4] = *(const float4*)&Bs[t][64 + (tx << 2)];
            u64 b2[4];
#pragma unroll
            for (int j = 0; j < 4; j++) b2[j] = pack2(bv[2 * j], bv[2 * j + 1]);
#pragma unroll
            for (int i = 0; i < 8; i++) {
                u64 a2 = pack2(a[i], a[i]);
#pragma unroll
                for (int j = 0; j < 4; j++) fma2(acc2[i][j], a2, b2[j]);
            }
        }
        __syncthreads();
    }

    float acc[8][8];
#pragma unroll
    for (int i = 0; i < 8; i++)
#pragma unroll
        for (int j = 0; j < 4; j++) {
            float2 f = unpack2(acc2[i][j]);
            acc[i][2 * j] = f.x; acc[i][2 * j + 1] = f.y;
        }

    // epilogue: 8 chunks of 16 cols, staged through smem, coalesced T stores
    int cgbase = col0 >> 2;
#pragma unroll
    for (int cc = 0; cc < 8; cc++) {
        __syncthreads();
        bool hi = (cc >= 4);
        int txlo = (cc & 3) << 2;
        if (tx >= txlo && tx < txlo + 4) {
#pragma unroll
            for (int i = 0; i < 8; i++) {
                int rl = (i < 4) ? ((ty << 2) + i) : (64 + (ty << 2) + i - 4);
#pragma unroll
                for (int jj = 0; jj < 4; jj++) {
                    int j = hi ? (jj + 4) : jj;
                    int wc_ = ((tx - txlo) << 2) + jj;
                    buf[rl][wc_] = acc[i][j];
                }
            }
        }
        __syncthreads();
#pragma unroll
        for (int v = 0; v < 2; v++) {
            int idx = tid + (v << 8);
            int pt = idx & 127, cgl = idx >> 7;
            float4 val = make_float4(buf[pt][cgl * 4 + 0], buf[pt][cgl * 4 + 1],
                                     buf[pt][cgl * 4 + 2], buf[pt][cgl * 4 + 3]);
            qpT4[(size_t)(cgbase + (cc << 2) + cgl) * NPTS + row0 + pt] = val;
        }
    }
}

// ---------------- gather-max, smem-staged, T in / T out ------------------------
// grid (c4, BB). Block stages its contiguous 2048-point q-slice (32KB), neighbor
// maxes from smem, writes dst4[d][point] coalesced.
__global__ void __launch_bounds__(256)
gather_kernel(const float4* __restrict__ qpT4, const int* __restrict__ idx,
              const float4* __restrict__ bias4, float4* __restrict__ dst4,
              int c4, int relu) {
    __shared__ __align__(16) float4 qs[NN];
    int d = blockIdx.x, b = blockIdx.y;
    size_t base = (size_t)b * NN;

    for (int i = threadIdx.x; i < NN; i += 256)
        qs[i] = qpT4[(size_t)d * NPTS + base + i];
    __syncthreads();

    float4 bb = bias4[d];
#pragma unroll
    for (int u = 0; u < NN / 256; u++) {
        int p = (int)base + threadIdx.x + (u << 8);
        const int4* ip = (const int4*)(idx + (size_t)p * KNBR);
        float4 m = make_float4(-FLT_MAX, -FLT_MAX, -FLT_MAX, -FLT_MAX);
#pragma unroll
        for (int w = 0; w < 8; w++) {
            int4 nb = ip[w];
            m = max4(m, qs[nb.x]);
            m = max4(m, qs[nb.y]);
            m = max4(m, qs[nb.z]);
            m = max4(m, qs[nb.w]);
        }
        float4 pp = qpT4[(size_t)(c4 + d) * NPTS + p];
        float4 r;
        r.x = pp.x + bb.x + m.x; r.y = pp.y + bb.y + m.y;
        r.z = pp.z + bb.z + m.z; r.w = pp.w + bb.w + m.w;
        if (relu) {
            r.x = fmaxf(r.x, 0.f); r.y = fmaxf(r.y, 0.f);
            r.z = fmaxf(r.z, 0.f); r.w = fmaxf(r.w, 0.f);
        }
        dst4[(size_t)d * NPTS + p] = r;
    }
}

// ---------------- final transpose: outT[cg][point] -> out[point][512] ----------
__global__ void __launch_bounds__(256)
transT_kernel(const float4* __restrict__ outT4, float4* __restrict__ out4) {
    __shared__ float4 tile[32][33];
    int p0 = blockIdx.x * 32, d0 = blockIdx.y * 32;
    int tx = threadIdx.x & 31, ty = threadIdx.x >> 5;   // ty 0..7
#pragma unroll
    for (int u = 0; u < 4; u++) {
        int d = d0 + ty + (u << 3);
        tile[ty + (u << 3)][tx] = outT4[(size_t)d * NPTS + p0 + tx];
    }
    __syncthreads();
#pragma unroll
    for (int u = 0; u < 4; u++) {
        int p = p0 + ty + (u << 3);
        out4[(size_t)p * 128 + d0 + tx] = tile[tx][ty + (u << 3)];
    }
}

// ---------------- launch (round-9 two-stream schedule, no concat) --------------
extern "C" void kernel_launch(void* const* d_in, const int* in_sizes, int n_in,
                              void* d_out, int out_size) {
    const float* x  = (const float*)d_in[0];
    const float* W1 = (const float*)d_in[1];
    const float* b1 = (const float*)d_in[2];
    const float* W2 = (const float*)d_in[3];
    const float* b2 = (const float*)d_in[4];
    const float* W3 = (const float*)d_in[5];
    const float* b3 = (const float*)d_in[6];
    float* out = (float*)d_out;

    float *sqp, *xc, *qp, *wc;
    unsigned* keys;
    int* idxp;
    cudaGetSymbolAddress((void**)&keys, g_keys);
    cudaGetSymbolAddress((void**)&sqp,  g_sq);
    cudaGetSymbolAddress((void**)&idxp, g_idx);
    cudaGetSymbolAddress((void**)&xc,   g_xc);
    cudaGetSymbolAddress((void**)&qp,   g_qp);
    cudaGetSymbolAddress((void**)&wc,   g_wc);
    float4* qpT4 = (float4*)qp;
    float4* xcT4 = (float4*)xc;           // 48 cgs: x1T = 0..15, x2T = 16..47
    float4* x1T4 = xcT4;
    float4* x2T4 = xcT4 + (size_t)16 * NPTS;
    float4* outT4 = (float4*)keys;        // stage-3 gather scratch (keys dead by then)

    float* wc3 = wc;            // 192*1024
    float* wc2 = wc + 196608;   // 64*256
    float* wc1 = wc + 212992;   // 3*128

    static cudaStream_t s1 = nullptr;
    static cudaEvent_t ev[8];
    if (!s1) {
        cudaStreamCreateWithFlags(&s1, cudaStreamNonBlocking);
        for (int i = 0; i < 8; i++) cudaEventCreateWithFlags(&ev[i], cudaEventDisableTiming);
    }

    dim3 symgrid(NPAIR, BB);

    // fork: side stream handles weight prep + feature GEMM chain
    cudaEventRecord(ev[0], 0);
    cudaStreamWaitEvent(s1, ev[0], 0);

    prepw_kernel<<<(3 * 64 + 255) / 256, 256, 0, s1>>>(W1, wc1, 3, 64);
    prepw_kernel<<<(64 * 128 + 255) / 256, 256, 0, s1>>>(W2, wc2, 64, 128);
    prepw_kernel<<<(192 * 512 + 255) / 256, 256, 0, s1>>>(W3, wc3, 192, 512);
    gemm_kernel<<<dim3(1, NPTS / 128), 256, 0, s1>>>(x, nullptr, wc1, qpT4, 3, 128, 0);
    cudaEventRecord(ev[1], s1);

    // ---- stage 1 selection chain (default stream)
    sq_kernel<<<(NPTS + 255) / 256, 256>>>(x, sqp, 3);
    d2sym_kernel<<<symgrid, 256>>>(x, nullptr, sqp, keys, 3);
    knn_kernel<<<NPTS, 256>>>(keys, idxp);
    cudaStreamWaitEvent(0, ev[1], 0);
    gather_kernel<<<dim3(16, BB), 256>>>(qpT4, idxp, (const float4*)b1, x1T4, 16, 1);
    cudaEventRecord(ev[2], 0);                 // x1T ready, qp free

    // side: gemm2 (reads x1T, writes qpT)
    cudaStreamWaitEvent(s1, ev[2], 0);
    gemm_kernel<<<dim3(2, NPTS / 128), 256, 0, s1>>>(nullptr, x1T4, wc2, qpT4, 64, 256, 1);
    cudaEventRecord(ev[3], s1);

    // ---- stage 2 selection chain
    sqT_kernel<<<(NPTS + 255) / 256, 256>>>(x1T4, sqp, 16);
    d2sym_kernel<<<symgrid, 256>>>(nullptr, x1T4, sqp, keys, 64);
    knn_kernel<<<NPTS, 256>>>(keys, idxp);
    cudaStreamWaitEvent(0, ev[3], 0);
    gather_kernel<<<dim3(32, BB), 256>>>(qpT4, idxp, (const float4*)b2, x2T4, 32, 1);
    cudaEventRecord(ev[4], 0);                 // x2T ready, qp free

    // side: gemm3 (reads xcT full 48 cgs, writes qpT) — concat eliminated
    cudaStreamWaitEvent(s1, ev[4], 0);
    gemm_kernel<<<dim3(8, NPTS / 128), 256, 0, s1>>>(nullptr, xcT4, wc3, qpT4, 192, 1024, 1);
    cudaEventRecord(ev[5], s1);

    // ---- stage 3 selection chain
    sqT_kernel<<<(NPTS + 255) / 256, 256>>>(x2T4, sqp, 32);
    d2sym_kernel<<<symgrid, 256>>>(nullptr, x2T4, sqp, keys, 128);
    knn_kernel<<<NPTS, 256>>>(keys, idxp);
    cudaStreamWaitEvent(0, ev[5], 0);
    gather_kernel<<<dim3(128, BB), 256>>>(qpT4, idxp, (const float4*)b3, outT4, 128, 0);
    transT_kernel<<<dim3(NPTS / 32, 4), 256>>>(outT4, (float4*)out);
}